// round 8
// baseline (speedup 1.0000x reference)
#include <cuda_runtime.h>
#include <cuda_fp16.h>
#include <math.h>
#include <stdint.h>

#define T_SEQ 2048
#define N_EMBD 2048
#define N_HEADS 16
#define N_GROUPS 4
#define HEAD_SIZE 128
#define INTER 5632
#define VOCAB 32000
#define QKV_DIM 3072

// ---------------- scratch ---------------------------------------------------
__device__ float g_x  [T_SEQ * N_EMBD];
__device__ float g_n  [T_SEQ * N_EMBD];
__device__ float g_qkv[T_SEQ * QKV_DIM];
__device__ float g_q  [N_HEADS  * T_SEQ * HEAD_SIZE];
__device__ float g_k  [N_GROUPS * T_SEQ * HEAD_SIZE];
__device__ float g_vT [N_GROUPS * HEAD_SIZE * T_SEQ];
__device__ float g_S  [N_HEADS * T_SEQ * T_SEQ];
__device__ float g_y  [T_SEQ * N_EMBD];
__device__ float g_h1 [T_SEQ * INTER];
__device__ float g_h2 [T_SEQ * INTER];

// ---------------- helpers ---------------------------------------------------
__device__ __forceinline__ uint32_t cvta_smem(const void* p) {
    uint32_t a;
    asm("{.reg .u64 t; cvta.to.shared.u64 t, %1; cvt.u32.u64 %0, t;}" : "=r"(a) : "l"(p));
    return a;
}

__device__ __forceinline__ void mma16(float* d, const uint32_t* a, const uint32_t* b) {
    asm volatile(
        "mma.sync.aligned.m16n8k16.row.col.f32.f16.f16.f32 "
        "{%0,%1,%2,%3}, {%4,%5,%6,%7}, {%8,%9}, {%0,%1,%2,%3};"
        : "+f"(d[0]), "+f"(d[1]), "+f"(d[2]), "+f"(d[3])
        : "r"(a[0]), "r"(a[1]), "r"(a[2]), "r"(a[3]), "r"(b[0]), "r"(b[1]));
}

__device__ __forceinline__ void ldsm4(uint32_t* r, uint32_t addr) {
    asm volatile("ldmatrix.sync.aligned.m8n8.x4.shared.b16 {%0,%1,%2,%3}, [%4];"
        : "=r"(r[0]), "=r"(r[1]), "=r"(r[2]), "=r"(r[3]) : "r"(addr));
}

__device__ __forceinline__ void split4(float4 v, uint2& hi, uint2& lo) {
    __half2 h01 = __floats2half2_rn(v.x, v.y);
    __half2 h23 = __floats2half2_rn(v.z, v.w);
    float2 f01 = __half22float2(h01);
    float2 f23 = __half22float2(h23);
    __half2 l01 = __floats2half2_rn(v.x - f01.x, v.y - f01.y);
    __half2 l23 = __floats2half2_rn(v.z - f23.x, v.w - f23.y);
    hi.x = *(uint32_t*)&h01; hi.y = *(uint32_t*)&h23;
    lo.x = *(uint32_t*)&l01; lo.y = *(uint32_t*)&l23;
}
__device__ __forceinline__ void trunc4(float4 v, uint2& hi) {
    __half2 h01 = __floats2half2_rn(v.x, v.y);
    __half2 h23 = __floats2half2_rn(v.z, v.w);
    hi.x = *(uint32_t*)&h01; hi.y = *(uint32_t*)&h23;
}

// ---------------- fp16 split NT GEMM (mma.sync m16n8k16 + ldmatrix) ---------
// C = A@B^T (+addC). TERMS=3: AhBh+AhBl+AlBh; TERMS=2: AhBh+AlBh; TERMS=1: AhBh.
// GLU=1: A := silu(A) * A2 elementwise (fused swiglu), computed in loader.
// mode: 0 plain
//       1 causal S: skip tiles above diagonal, epilogue scale+mask
//       2 causal PV: K clamped at diagonal; fp32 pre-pass row-sums of A,
//         rows scaled by 1/(rowsum+1e-8) (linear-attention normalize)
#define BMT 128
#define BNT 128
#define KB  32
#define ROWW 20
#define SUBW (128 * ROWW)

template<int TERMS, int GLU>
__global__ void __launch_bounds__(256)
gemm_f16(const float* __restrict__ A, const float* __restrict__ A2, int lda, long long sA,
         const float* __restrict__ B, int ldb, long long sB, int bdiv,
         float* C, int ldc, long long sC,
         const float* __restrict__ addC,
         int K, int mode, float scaleC)
{
    constexpr int NA   = (TERMS >= 2) ? 2 : 1;
    constexpr int NSUB = NA + ((TERMS == 3) ? 2 : 1);
    constexpr int STGW = NSUB * SUBW;
    extern __shared__ __align__(16) uint32_t smw[];
    const int m0 = blockIdx.x * BMT;
    const int n0 = blockIdx.y * BNT;
    if (mode == 1 && n0 > m0 + BMT - 1) return;
    const int Keff = (mode == 2) ? min(K, m0 + BMT) : K;
    const int KT = Keff / KB;
    const int z = blockIdx.z;
    A += (long long)z * sA;
    B += (long long)(z / bdiv) * sB;
    const long long coff = (long long)z * sC;

    const int tid  = threadIdx.x;
    const int lane = tid & 31;
    const int wid  = tid >> 5;
    const int wm   = (wid & 1) * 64;
    const int wn   = (wid >> 1) * 32;
    const uint32_t sbase = cvta_smem(smw);

    const int aRow  = wm + (lane & 15);
    const int aCol4 = (lane & 16) ? 4 : 0;
    const int bRow  = wn + (lane & 7) + ((lane & 16) ? 8 : 0);
    const int bCol4 = (lane & 8) ? 4 : 0;

    float4 rA[4], rB[4];
    const int lr = tid >> 3;
    const int lc = tid & 7;

    // ---- mode 2: deterministic fp32 row-sum pre-pass over A strip ----
    float ascale[4] = {1.f, 1.f, 1.f, 1.f};
    if (mode == 2) {
        float rs[4] = {0.f, 0.f, 0.f, 0.f};
        for (int kt = 0; kt < KT; kt++) {
            #pragma unroll
            for (int it = 0; it < 4; it++) {
                int r = it * 32 + lr;
                float4 v = *(const float4*)(A + (long long)(m0 + r) * lda + kt * KB + lc * 4);
                rs[it] += (v.x + v.y) + (v.z + v.w);
            }
        }
        #pragma unroll
        for (int it = 0; it < 4; it++) {
            #pragma unroll
            for (int o = 1; o < 8; o <<= 1)
                rs[it] += __shfl_xor_sync(0xffffffffu, rs[it], o);
            ascale[it] = 1.f / (rs[it] + 1e-8f);
        }
    }

    auto ldg_tile = [&](int kt) {
        #pragma unroll
        for (int it = 0; it < 4; it++) {
            int r = it * 32 + lr;
            float4 a = *(const float4*)(A + (long long)(m0 + r) * lda + kt * KB + lc * 4);
            if (GLU) {
                float4 b = *(const float4*)(A2 + (long long)(m0 + r) * lda + kt * KB + lc * 4);
                a.x = a.x / (1.f + expf(-a.x)) * b.x;
                a.y = a.y / (1.f + expf(-a.y)) * b.y;
                a.z = a.z / (1.f + expf(-a.z)) * b.z;
                a.w = a.w / (1.f + expf(-a.w)) * b.w;
            }
            rA[it] = a;
            rB[it] = *(const float4*)(B + (long long)(n0 + r) * ldb + kt * KB + lc * 4);
        }
    };
    auto sts_tile = [&](int s) {
        uint32_t* st = smw + s * STGW;
        #pragma unroll
        for (int it = 0; it < 4; it++) {
            int r = it * 32 + lr;
            int w = r * ROWW + lc * 2;
            float4 av = rA[it];
            if (mode == 2) { av.x *= ascale[it]; av.y *= ascale[it]; av.z *= ascale[it]; av.w *= ascale[it]; }
            uint2 hi, lo;
            if (TERMS >= 2) {
                split4(av, hi, lo);
                *(uint2*)(st + w) = hi;
                *(uint2*)(st + SUBW + w) = lo;
            } else {
                trunc4(av, hi);
                *(uint2*)(st + w) = hi;
            }
            if (TERMS == 3) {
                split4(rB[it], hi, lo);
                *(uint2*)(st + NA * SUBW + w) = hi;
                *(uint2*)(st + (NA + 1) * SUBW + w) = lo;
            } else {
                trunc4(rB[it], hi);
                *(uint2*)(st + NA * SUBW + w) = hi;
            }
        }
    };

    float acc[4][4][4];
    #pragma unroll
    for (int a = 0; a < 4; a++)
        #pragma unroll
        for (int b = 0; b < 4; b++)
            #pragma unroll
            for (int c = 0; c < 4; c++) acc[a][b][c] = 0.f;

    ldg_tile(0);
    sts_tile(0);
    if (KT > 1) ldg_tile(1);
    __syncthreads();

    for (int kt = 0; kt < KT; kt++) {
        if (kt + 1 < KT) sts_tile((kt + 1) & 1);
        if (kt + 2 < KT) ldg_tile(kt + 2);

        const uint32_t stAddr = sbase + (uint32_t)((kt & 1) * STGW) * 4u;

        #pragma unroll
        for (int ks = 0; ks < 2; ks++) {
            uint32_t Ah[4][4], Al[4][4], Bh[4][2], Bl[4][2];
            #pragma unroll
            for (int mc = 0; mc < 4; mc++) {
                uint32_t off = stAddr + (uint32_t)(((aRow + mc * 16) * ROWW + aCol4 + ks * 8)) * 4u;
                ldsm4(Ah[mc], off);
                if (TERMS >= 2) ldsm4(Al[mc], off + SUBW * 4u);
            }
            #pragma unroll
            for (int ncp = 0; ncp < 2; ncp++) {
                uint32_t off = stAddr + (uint32_t)((NA * SUBW + (bRow + ncp * 16) * ROWW + bCol4 + ks * 8)) * 4u;
                uint32_t t[4];
                ldsm4(t, off);
                Bh[ncp * 2][0] = t[0]; Bh[ncp * 2][1] = t[1];
                Bh[ncp * 2 + 1][0] = t[2]; Bh[ncp * 2 + 1][1] = t[3];
                if (TERMS == 3) {
                    ldsm4(t, off + SUBW * 4u);
                    Bl[ncp * 2][0] = t[0]; Bl[ncp * 2][1] = t[1];
                    Bl[ncp * 2 + 1][0] = t[2]; Bl[ncp * 2 + 1][1] = t[3];
                }
            }
            #pragma unroll
            for (int mc = 0; mc < 4; mc++)
                #pragma unroll
                for (int nc = 0; nc < 4; nc++) {
                    mma16(acc[mc][nc], Ah[mc], Bh[nc]);
                    if (TERMS == 3) mma16(acc[mc][nc], Ah[mc], Bl[nc]);
                    if (TERMS >= 2) mma16(acc[mc][nc], Al[mc], Bh[nc]);
                }
        }
        __syncthreads();
    }

    // ---- epilogue ----
    #pragma unroll
    for (int mc = 0; mc < 4; mc++)
        #pragma unroll
        for (int nc = 0; nc < 4; nc++) {
            int c0 = n0 + wn + nc * 8 + (lane & 3) * 2;
            #pragma unroll
            for (int rr = 0; rr < 2; rr++) {
                int row = m0 + wm + mc * 16 + (lane >> 2) + rr * 8;
                float v0 = acc[mc][nc][rr * 2] * scaleC;
                float v1 = acc[mc][nc][rr * 2 + 1] * scaleC;
                if (mode == 1) {
                    if (c0 > row)     v0 = 0.f;
                    if (c0 + 1 > row) v1 = 0.f;
                }
                long long off = coff + (long long)row * ldc + c0;
                if (addC) { v0 += addC[off]; v1 += addC[off + 1]; }
                C[off] = v0;
                C[off + 1] = v1;
            }
        }
}

// ---------------- elementwise kernels ---------------------------------------
__global__ void embed_kernel(const int* __restrict__ idx,
                             const float* __restrict__ wte, float* __restrict__ x)
{
    int t = blockIdx.x;
    const float* src = wte + (long long)idx[t] * N_EMBD;
    float* dst = x + (long long)t * N_EMBD;
    for (int e = threadIdx.x; e < N_EMBD; e += blockDim.x) dst[e] = src[e];
}

__global__ void rmsnorm_kernel(const float* __restrict__ x, const float* __restrict__ w,
                               float* __restrict__ out)
{
    int t = blockIdx.x;
    const float* row = x + (long long)t * N_EMBD;
    float s = 0.f;
    for (int e = threadIdx.x; e < N_EMBD; e += blockDim.x) { float v = row[e]; s += v * v; }
    __shared__ float red[32];
    #pragma unroll
    for (int o = 16; o; o >>= 1) s += __shfl_xor_sync(0xffffffffu, s, o);
    if ((threadIdx.x & 31) == 0) red[threadIdx.x >> 5] = s;
    __syncthreads();
    if (threadIdx.x < 32) {
        float v = (threadIdx.x < (blockDim.x >> 5)) ? red[threadIdx.x] : 0.f;
        #pragma unroll
        for (int o = 16; o; o >>= 1) v += __shfl_xor_sync(0xffffffffu, v, o);
        if (threadIdx.x == 0) red[0] = v;
    }
    __syncthreads();
    float r = rsqrtf(red[0] * (1.f / N_EMBD) + 1e-5f);
    float* dst = out + (long long)t * N_EMBD;
    for (int e = threadIdx.x; e < N_EMBD; e += blockDim.x)
        dst[e] = row[e] * r * w[e];
}

__global__ void qkv_post_kernel(const float* __restrict__ qkv,
                                float* __restrict__ q,
                                float* __restrict__ k,
                                float* __restrict__ vT)
{
    int t = blockIdx.x;
    const float LN_BASE = 9.210340371976184f;
    for (int i = threadIdx.x; i < N_GROUPS * 6 * 64; i += blockDim.x) {
        int j    = i & 63;
        int slot = (i >> 6) % 6;
        int g    = i / (6 * 64);
        const float* src = qkv + (long long)t * QKV_DIM + (g * 6 + slot) * HEAD_SIZE;
        float x1 = src[j];
        float x2 = src[j + 64];
        if (slot < 5) {
            float theta = expf(-(2.f * j / 128.f) * LN_BASE);
            float ang = (float)t * theta;
            float sv, cv;
            sincosf(ang, &sv, &cv);
            float o1 = x1 * cv - x2 * sv;
            float o2 = x1 * sv + x2 * cv;
            o1 = (o1 > 0.f) ? (o1 + 1.f) : expf(o1);
            o2 = (o2 > 0.f) ? (o2 + 1.f) : expf(o2);
            if (slot < 4) {
                int h = g * 4 + slot;
                float* dst = q + ((long long)h * T_SEQ + t) * HEAD_SIZE;
                dst[j] = o1; dst[j + 64] = o2;
            } else {
                float* dst = k + ((long long)g * T_SEQ + t) * HEAD_SIZE;
                dst[j] = o1; dst[j + 64] = o2;
            }
        } else {
            vT[((long long)g * HEAD_SIZE + j) * T_SEQ + t]      = x1;
            vT[((long long)g * HEAD_SIZE + j + 64) * T_SEQ + t] = x2;
        }
    }
}

// ---------------- orchestration ---------------------------------------------
extern "C" void kernel_launch(void* const* d_in, const int* in_sizes, int n_in,
                              void* d_out, int out_size)
{
    const int*   idx       = (const int*)  d_in[0];
    const float* wte       = (const float*)d_in[1];
    const float* attn_w    = (const float*)d_in[2];
    const float* proj_w    = (const float*)d_in[3];
    const float* w1        = (const float*)d_in[4];
    const float* w2        = (const float*)d_in[5];
    const float* w3        = (const float*)d_in[6];
    const float* norm1_w   = (const float*)d_in[7];
    const float* norm2_w   = (const float*)d_in[8];
    const float* ln_f_w    = (const float*)d_in[9];
    const float* lm_head_w = (const float*)d_in[10];
    float* out = (float*)d_out;

    float *x, *n, *qkv, *q, *k, *vT, *S, *y, *h1, *h2;
    cudaGetSymbolAddress((void**)&x,   g_x);
    cudaGetSymbolAddress((void**)&n,   g_n);
    cudaGetSymbolAddress((void**)&qkv, g_qkv);
    cudaGetSymbolAddress((void**)&q,   g_q);
    cudaGetSymbolAddress((void**)&k,   g_k);
    cudaGetSymbolAddress((void**)&vT,  g_vT);
    cudaGetSymbolAddress((void**)&S,   g_S);
    cudaGetSymbolAddress((void**)&y,   g_y);
    cudaGetSymbolAddress((void**)&h1,  g_h1);
    cudaGetSymbolAddress((void**)&h2,  g_h2);

    const int SMEM2 = 2 * 3 * SUBW * 4;   // 61440 B
    const int SMEM1 = 2 * 2 * SUBW * 4;   // 40960 B
    cudaFuncSetAttribute((gemm_f16<2, 0>), cudaFuncAttributeMaxDynamicSharedMemorySize, SMEM2);
    cudaFuncSetAttribute((gemm_f16<2, 1>), cudaFuncAttributeMaxDynamicSharedMemorySize, SMEM2);
    cudaFuncSetAttribute((gemm_f16<1, 0>), cudaFuncAttributeMaxDynamicSharedMemorySize, SMEM1);

    const long long TT = (long long)T_SEQ * T_SEQ;
    const long long TH = (long long)T_SEQ * HEAD_SIZE;
    const float SSCALE = 0.08838834764831845f;   // 1/sqrt(128)

    embed_kernel<<<T_SEQ, 256>>>(idx, wte, x);

    for (int l = 0; l < 2; l++) {
        const float* aw  = attn_w + (long long)l * QKV_DIM * N_EMBD;
        const float* pw  = proj_w + (long long)l * N_EMBD * N_EMBD;
        const float* w1l = w1 + (long long)l * INTER * N_EMBD;
        const float* w2l = w2 + (long long)l * INTER * N_EMBD;
        const float* w3l = w3 + (long long)l * N_EMBD * INTER;

        rmsnorm_kernel<<<T_SEQ, 256>>>(x, norm1_w + l * N_EMBD, n);

        // qkv = n1 @ attn_w^T  (2-term)
        gemm_f16<2, 0><<<dim3(T_SEQ / BMT, QKV_DIM / BNT, 1), 256, SMEM2>>>(
            n, nullptr, N_EMBD, 0, aw, N_EMBD, 0, 1,
            qkv, QKV_DIM, 0, nullptr, N_EMBD, 0, 1.f);

        qkv_post_kernel<<<T_SEQ, 512>>>(qkv, q, k, vT);

        // S[h] = mask(q[h] @ k[g]^T * scale)  (2-term, fused mask+scale)
        gemm_f16<2, 0><<<dim3(T_SEQ / BMT, T_SEQ / BNT, N_HEADS), 256, SMEM2>>>(
            q, nullptr, HEAD_SIZE, TH, k, HEAD_SIZE, TH, 4,
            S, T_SEQ, TT, nullptr, HEAD_SIZE, 1, SSCALE);

        // y[:, h] = (S/rowsum)[h] @ vT[g]^T  (2-term, fused normalize)
        gemm_f16<2, 0><<<dim3(T_SEQ / BMT, HEAD_SIZE / BNT, N_HEADS), 256, SMEM2>>>(
            S, nullptr, T_SEQ, TT, vT, T_SEQ, (long long)HEAD_SIZE * T_SEQ, 4,
            y, N_EMBD, HEAD_SIZE, nullptr, T_SEQ, 2, 1.f);

        // x = x + y @ proj_w^T  (2-term)
        gemm_f16<2, 0><<<dim3(T_SEQ / BMT, N_EMBD / BNT, 1), 256, SMEM2>>>(
            y, nullptr, N_EMBD, 0, pw, N_EMBD, 0, 1,
            x, N_EMBD, 0, x, N_EMBD, 0, 1.f);

        rmsnorm_kernel<<<T_SEQ, 256>>>(x, norm2_w + l * N_EMBD, n);

        // MLP up projections (2-term)
        gemm_f16<2, 0><<<dim3(T_SEQ / BMT, INTER / BNT, 1), 256, SMEM2>>>(
            n, nullptr, N_EMBD, 0, w1l, N_EMBD, 0, 1,
            h1, INTER, 0, nullptr, N_EMBD, 0, 1.f);
        gemm_f16<2, 0><<<dim3(T_SEQ / BMT, INTER / BNT, 1), 256, SMEM2>>>(
            n, nullptr, N_EMBD, 0, w2l, N_EMBD, 0, 1,
            h2, INTER, 0, nullptr, N_EMBD, 0, 1.f);

        // x = x + swiglu(h1, h2) @ w3^T  (2-term, fused GLU in loader)
        gemm_f16<2, 1><<<dim3(T_SEQ / BMT, N_EMBD / BNT, 1), 256, SMEM2>>>(
            h1, h2, INTER, 0, w3l, INTER, 0, 1,
            x, N_EMBD, 0, x, INTER, 0, 1.f);
    }

    rmsnorm_kernel<<<T_SEQ, 256>>>(x, ln_f_w, n);
    // lm_head: 1-term fp16
    gemm_f16<1, 0><<<dim3(T_SEQ / BMT, VOCAB / BNT, 1), 256, SMEM1>>>(
        n, nullptr, N_EMBD, 0, lm_head_w, N_EMBD, 0, 1,
        out, VOCAB, 0, nullptr, N_EMBD, 0, 1.f);
}

// round 9
// speedup vs baseline: 1.1122x; 1.1122x over previous
#include <cuda_runtime.h>
#include <cuda_fp16.h>
#include <math.h>
#include <stdint.h>

#define T_SEQ 2048
#define N_EMBD 2048
#define N_HEADS 16
#define N_GROUPS 4
#define HEAD_SIZE 128
#define INTER 5632
#define VOCAB 32000
#define QKV_DIM 3072

// ---------------- scratch ---------------------------------------------------
__device__ float g_x  [T_SEQ * N_EMBD];
__device__ float g_n  [T_SEQ * N_EMBD];
__device__ float g_qkv[T_SEQ * QKV_DIM];
__device__ float g_q  [N_HEADS  * T_SEQ * HEAD_SIZE];
__device__ float g_k  [N_GROUPS * T_SEQ * HEAD_SIZE];
__device__ float g_vT [N_GROUPS * HEAD_SIZE * T_SEQ];
__device__ float g_S  [N_HEADS * T_SEQ * T_SEQ];
__device__ float g_y  [T_SEQ * N_EMBD];
__device__ float g_h1 [T_SEQ * INTER];
__device__ float g_h2 [T_SEQ * INTER];

// ---------------- helpers ---------------------------------------------------
__device__ __forceinline__ uint32_t cvta_smem(const void* p) {
    uint32_t a;
    asm("{.reg .u64 t; cvta.to.shared.u64 t, %1; cvt.u32.u64 %0, t;}" : "=r"(a) : "l"(p));
    return a;
}

__device__ __forceinline__ void mma16(float* d, const uint32_t* a, const uint32_t* b) {
    asm volatile(
        "mma.sync.aligned.m16n8k16.row.col.f32.f16.f16.f32 "
        "{%0,%1,%2,%3}, {%4,%5,%6,%7}, {%8,%9}, {%0,%1,%2,%3};"
        : "+f"(d[0]), "+f"(d[1]), "+f"(d[2]), "+f"(d[3])
        : "r"(a[0]), "r"(a[1]), "r"(a[2]), "r"(a[3]), "r"(b[0]), "r"(b[1]));
}

__device__ __forceinline__ void ldsm4(uint32_t* r, uint32_t addr) {
    asm volatile("ldmatrix.sync.aligned.m8n8.x4.shared.b16 {%0,%1,%2,%3}, [%4];"
        : "=r"(r[0]), "=r"(r[1]), "=r"(r[2]), "=r"(r[3]) : "r"(addr));
}

__device__ __forceinline__ void split4(float4 v, uint2& hi, uint2& lo) {
    __half2 h01 = __floats2half2_rn(v.x, v.y);
    __half2 h23 = __floats2half2_rn(v.z, v.w);
    float2 f01 = __half22float2(h01);
    float2 f23 = __half22float2(h23);
    __half2 l01 = __floats2half2_rn(v.x - f01.x, v.y - f01.y);
    __half2 l23 = __floats2half2_rn(v.z - f23.x, v.w - f23.y);
    hi.x = *(uint32_t*)&h01; hi.y = *(uint32_t*)&h23;
    lo.x = *(uint32_t*)&l01; lo.y = *(uint32_t*)&l23;
}
__device__ __forceinline__ void trunc4(float4 v, uint2& hi) {
    __half2 h01 = __floats2half2_rn(v.x, v.y);
    __half2 h23 = __floats2half2_rn(v.z, v.w);
    hi.x = *(uint32_t*)&h01; hi.y = *(uint32_t*)&h23;
}

// ---------------- fp16 split NT GEMM (mma.sync m16n8k16 + ldmatrix) ---------
// C = A@B^T (+addC). TERMS=2: AhBh+AlBh (A split, B truncated); TERMS=1: AhBh.
// mode: 0 plain
//       1 causal S: skip tiles above diagonal, epilogue scale+mask
//       2 causal PV: K clamped at diagonal; fp32 pre-pass row-sums of A,
//         rows scaled by 1/(rowsum+1e-8) (linear-attention normalize)
#define BMT 128
#define BNT 128
#define KB  32
#define ROWW 20
#define SUBW (128 * ROWW)

template<int TERMS>
__global__ void __launch_bounds__(256)
gemm_f16(const float* __restrict__ A, int lda, long long sA,
         const float* __restrict__ B, int ldb, long long sB, int bdiv,
         float* C, int ldc, long long sC,
         const float* __restrict__ addC,
         int K, int mode, float scaleC)
{
    constexpr int NA   = (TERMS >= 2) ? 2 : 1;
    constexpr int NSUB = NA + 1;
    constexpr int STGW = NSUB * SUBW;
    extern __shared__ __align__(16) uint32_t smw[];
    const int m0 = blockIdx.x * BMT;
    const int n0 = blockIdx.y * BNT;
    if (mode == 1 && n0 > m0 + BMT - 1) return;
    const int Keff = (mode == 2) ? min(K, m0 + BMT) : K;
    const int KT = Keff / KB;
    const int z = blockIdx.z;
    A += (long long)z * sA;
    B += (long long)(z / bdiv) * sB;
    const long long coff = (long long)z * sC;

    const int tid  = threadIdx.x;
    const int lane = tid & 31;
    const int wid  = tid >> 5;
    const int wm   = (wid & 1) * 64;
    const int wn   = (wid >> 1) * 32;
    const uint32_t sbase = cvta_smem(smw);

    const int aRow  = wm + (lane & 15);
    const int aCol4 = (lane & 16) ? 4 : 0;
    const int bRow  = wn + (lane & 7) + ((lane & 16) ? 8 : 0);
    const int bCol4 = (lane & 8) ? 4 : 0;

    float4 rA[4], rB[4];
    const int lr = tid >> 3;
    const int lc = tid & 7;

    // ---- mode 2: deterministic fp32 row-sum pre-pass over A strip ----
    float ascale[4] = {1.f, 1.f, 1.f, 1.f};
    if (mode == 2) {
        float rs[4] = {0.f, 0.f, 0.f, 0.f};
        for (int kt = 0; kt < KT; kt++) {
            #pragma unroll
            for (int it = 0; it < 4; it++) {
                int r = it * 32 + lr;
                float4 v = *(const float4*)(A + (long long)(m0 + r) * lda + kt * KB + lc * 4);
                rs[it] += (v.x + v.y) + (v.z + v.w);
            }
        }
        #pragma unroll
        for (int it = 0; it < 4; it++) {
            #pragma unroll
            for (int o = 1; o < 8; o <<= 1)
                rs[it] += __shfl_xor_sync(0xffffffffu, rs[it], o);
            ascale[it] = 1.f / (rs[it] + 1e-8f);
        }
    }

    auto ldg_tile = [&](int kt) {
        #pragma unroll
        for (int it = 0; it < 4; it++) {
            int r = it * 32 + lr;
            rA[it] = *(const float4*)(A + (long long)(m0 + r) * lda + kt * KB + lc * 4);
            rB[it] = *(const float4*)(B + (long long)(n0 + r) * ldb + kt * KB + lc * 4);
        }
    };
    auto sts_tile = [&](int s) {
        uint32_t* st = smw + s * STGW;
        #pragma unroll
        for (int it = 0; it < 4; it++) {
            int r = it * 32 + lr;
            int w = r * ROWW + lc * 2;
            float4 av = rA[it];
            if (mode == 2) { av.x *= ascale[it]; av.y *= ascale[it]; av.z *= ascale[it]; av.w *= ascale[it]; }
            uint2 hi, lo;
            if (TERMS >= 2) {
                split4(av, hi, lo);
                *(uint2*)(st + w) = hi;
                *(uint2*)(st + SUBW + w) = lo;
            } else {
                trunc4(av, hi);
                *(uint2*)(st + w) = hi;
            }
            trunc4(rB[it], hi);
            *(uint2*)(st + NA * SUBW + w) = hi;
        }
    };

    float acc[4][4][4];
    #pragma unroll
    for (int a = 0; a < 4; a++)
        #pragma unroll
        for (int b = 0; b < 4; b++)
            #pragma unroll
            for (int c = 0; c < 4; c++) acc[a][b][c] = 0.f;

    ldg_tile(0);
    sts_tile(0);
    if (KT > 1) ldg_tile(1);
    __syncthreads();

    for (int kt = 0; kt < KT; kt++) {
        if (kt + 1 < KT) sts_tile((kt + 1) & 1);
        if (kt + 2 < KT) ldg_tile(kt + 2);

        const uint32_t stAddr = sbase + (uint32_t)((kt & 1) * STGW) * 4u;

        #pragma unroll
        for (int ks = 0; ks < 2; ks++) {
            uint32_t Ah[4][4], Al[4][4], Bh[4][2];
            #pragma unroll
            for (int mc = 0; mc < 4; mc++) {
                uint32_t off = stAddr + (uint32_t)(((aRow + mc * 16) * ROWW + aCol4 + ks * 8)) * 4u;
                ldsm4(Ah[mc], off);
                if (TERMS >= 2) ldsm4(Al[mc], off + SUBW * 4u);
            }
            #pragma unroll
            for (int ncp = 0; ncp < 2; ncp++) {
                uint32_t off = stAddr + (uint32_t)((NA * SUBW + (bRow + ncp * 16) * ROWW + bCol4 + ks * 8)) * 4u;
                uint32_t t[4];
                ldsm4(t, off);
                Bh[ncp * 2][0] = t[0]; Bh[ncp * 2][1] = t[1];
                Bh[ncp * 2 + 1][0] = t[2]; Bh[ncp * 2 + 1][1] = t[3];
            }
            #pragma unroll
            for (int mc = 0; mc < 4; mc++)
                #pragma unroll
                for (int nc = 0; nc < 4; nc++) {
                    mma16(acc[mc][nc], Ah[mc], Bh[nc]);
                    if (TERMS >= 2) mma16(acc[mc][nc], Al[mc], Bh[nc]);
                }
        }
        __syncthreads();
    }

    // ---- epilogue ----
    #pragma unroll
    for (int mc = 0; mc < 4; mc++)
        #pragma unroll
        for (int nc = 0; nc < 4; nc++) {
            int c0 = n0 + wn + nc * 8 + (lane & 3) * 2;
            #pragma unroll
            for (int rr = 0; rr < 2; rr++) {
                int row = m0 + wm + mc * 16 + (lane >> 2) + rr * 8;
                float v0 = acc[mc][nc][rr * 2] * scaleC;
                float v1 = acc[mc][nc][rr * 2 + 1] * scaleC;
                if (mode == 1) {
                    if (c0 > row)     v0 = 0.f;
                    if (c0 + 1 > row) v1 = 0.f;
                }
                long long off = coff + (long long)row * ldc + c0;
                if (addC) { v0 += addC[off]; v1 += addC[off + 1]; }
                C[off] = v0;
                C[off + 1] = v1;
            }
        }
}

// ---------------- elementwise kernels ---------------------------------------
__global__ void embed_kernel(const int* __restrict__ idx,
                             const float* __restrict__ wte, float* __restrict__ x)
{
    int t = blockIdx.x;
    const float* src = wte + (long long)idx[t] * N_EMBD;
    float* dst = x + (long long)t * N_EMBD;
    for (int e = threadIdx.x; e < N_EMBD; e += blockDim.x) dst[e] = src[e];
}

__global__ void rmsnorm_kernel(const float* __restrict__ x, const float* __restrict__ w,
                               float* __restrict__ out)
{
    int t = blockIdx.x;
    const float* row = x + (long long)t * N_EMBD;
    float s = 0.f;
    for (int e = threadIdx.x; e < N_EMBD; e += blockDim.x) { float v = row[e]; s += v * v; }
    __shared__ float red[32];
    #pragma unroll
    for (int o = 16; o; o >>= 1) s += __shfl_xor_sync(0xffffffffu, s, o);
    if ((threadIdx.x & 31) == 0) red[threadIdx.x >> 5] = s;
    __syncthreads();
    if (threadIdx.x < 32) {
        float v = (threadIdx.x < (blockDim.x >> 5)) ? red[threadIdx.x] : 0.f;
        #pragma unroll
        for (int o = 16; o; o >>= 1) v += __shfl_xor_sync(0xffffffffu, v, o);
        if (threadIdx.x == 0) red[0] = v;
    }
    __syncthreads();
    float r = rsqrtf(red[0] * (1.f / N_EMBD) + 1e-5f);
    float* dst = out + (long long)t * N_EMBD;
    for (int e = threadIdx.x; e < N_EMBD; e += blockDim.x)
        dst[e] = row[e] * r * w[e];
}

__global__ void qkv_post_kernel(const float* __restrict__ qkv,
                                float* __restrict__ q,
                                float* __restrict__ k,
                                float* __restrict__ vT)
{
    int t = blockIdx.x;
    const float LN_BASE = 9.210340371976184f;
    for (int i = threadIdx.x; i < N_GROUPS * 6 * 64; i += blockDim.x) {
        int j    = i & 63;
        int slot = (i >> 6) % 6;
        int g    = i / (6 * 64);
        const float* src = qkv + (long long)t * QKV_DIM + (g * 6 + slot) * HEAD_SIZE;
        float x1 = src[j];
        float x2 = src[j + 64];
        if (slot < 5) {
            float theta = expf(-(2.f * j / 128.f) * LN_BASE);
            float ang = (float)t * theta;
            float sv, cv;
            sincosf(ang, &sv, &cv);
            float o1 = x1 * cv - x2 * sv;
            float o2 = x1 * sv + x2 * cv;
            o1 = (o1 > 0.f) ? (o1 + 1.f) : expf(o1);
            o2 = (o2 > 0.f) ? (o2 + 1.f) : expf(o2);
            if (slot < 4) {
                int h = g * 4 + slot;
                float* dst = q + ((long long)h * T_SEQ + t) * HEAD_SIZE;
                dst[j] = o1; dst[j + 64] = o2;
            } else {
                float* dst = k + ((long long)g * T_SEQ + t) * HEAD_SIZE;
                dst[j] = o1; dst[j + 64] = o2;
            }
        } else {
            vT[((long long)g * HEAD_SIZE + j) * T_SEQ + t]      = x1;
            vT[((long long)g * HEAD_SIZE + j + 64) * T_SEQ + t] = x2;
        }
    }
}

__global__ void swiglu_kernel(float* __restrict__ a, const float* __restrict__ b)
{
    long long i = (long long)blockIdx.x * blockDim.x + threadIdx.x;
    if (i < (long long)T_SEQ * INTER) {
        float x = a[i];
        float sig = 1.f / (1.f + expf(-x));
        a[i] = x * sig * b[i];
    }
}

// ---------------- orchestration ---------------------------------------------
extern "C" void kernel_launch(void* const* d_in, const int* in_sizes, int n_in,
                              void* d_out, int out_size)
{
    const int*   idx       = (const int*)  d_in[0];
    const float* wte       = (const float*)d_in[1];
    const float* attn_w    = (const float*)d_in[2];
    const float* proj_w    = (const float*)d_in[3];
    const float* w1        = (const float*)d_in[4];
    const float* w2        = (const float*)d_in[5];
    const float* w3        = (const float*)d_in[6];
    const float* norm1_w   = (const float*)d_in[7];
    const float* norm2_w   = (const float*)d_in[8];
    const float* ln_f_w    = (const float*)d_in[9];
    const float* lm_head_w = (const float*)d_in[10];
    float* out = (float*)d_out;

    float *x, *n, *qkv, *q, *k, *vT, *S, *y, *h1, *h2;
    cudaGetSymbolAddress((void**)&x,   g_x);
    cudaGetSymbolAddress((void**)&n,   g_n);
    cudaGetSymbolAddress((void**)&qkv, g_qkv);
    cudaGetSymbolAddress((void**)&q,   g_q);
    cudaGetSymbolAddress((void**)&k,   g_k);
    cudaGetSymbolAddress((void**)&vT,  g_vT);
    cudaGetSymbolAddress((void**)&S,   g_S);
    cudaGetSymbolAddress((void**)&y,   g_y);
    cudaGetSymbolAddress((void**)&h1,  g_h1);
    cudaGetSymbolAddress((void**)&h2,  g_h2);

    const int SMEM2 = 2 * 3 * SUBW * 4;   // 61440 B
    const int SMEM1 = 2 * 2 * SUBW * 4;   // 40960 B
    cudaFuncSetAttribute(gemm_f16<2>, cudaFuncAttributeMaxDynamicSharedMemorySize, SMEM2);
    cudaFuncSetAttribute(gemm_f16<1>, cudaFuncAttributeMaxDynamicSharedMemorySize, SMEM1);

    const long long TT = (long long)T_SEQ * T_SEQ;
    const long long TH = (long long)T_SEQ * HEAD_SIZE;
    const float SSCALE = 0.08838834764831845f;   // 1/sqrt(128)

    embed_kernel<<<T_SEQ, 256>>>(idx, wte, x);

    for (int l = 0; l < 2; l++) {
        const float* aw  = attn_w + (long long)l * QKV_DIM * N_EMBD;
        const float* pw  = proj_w + (long long)l * N_EMBD * N_EMBD;
        const float* w1l = w1 + (long long)l * INTER * N_EMBD;
        const float* w2l = w2 + (long long)l * INTER * N_EMBD;
        const float* w3l = w3 + (long long)l * N_EMBD * INTER;

        rmsnorm_kernel<<<T_SEQ, 256>>>(x, norm1_w + l * N_EMBD, n);

        // qkv = n1 @ attn_w^T  (2-term)
        gemm_f16<2><<<dim3(T_SEQ / BMT, QKV_DIM / BNT, 1), 256, SMEM2>>>(
            n, N_EMBD, 0, aw, N_EMBD, 0, 1,
            qkv, QKV_DIM, 0, nullptr, N_EMBD, 0, 1.f);

        qkv_post_kernel<<<T_SEQ, 512>>>(qkv, q, k, vT);

        // S[h] = mask(q[h] @ k[g]^T * scale)  (2-term, fused mask+scale)
        gemm_f16<2><<<dim3(T_SEQ / BMT, T_SEQ / BNT, N_HEADS), 256, SMEM2>>>(
            q, HEAD_SIZE, TH, k, HEAD_SIZE, TH, 4,
            S, T_SEQ, TT, nullptr, HEAD_SIZE, 1, SSCALE);

        // y[:, h] = (S/rowsum)[h] @ vT[g]^T  (2-term, fused normalize)
        gemm_f16<2><<<dim3(T_SEQ / BMT, HEAD_SIZE / BNT, N_HEADS), 256, SMEM2>>>(
            S, T_SEQ, TT, vT, T_SEQ, (long long)HEAD_SIZE * T_SEQ, 4,
            y, N_EMBD, HEAD_SIZE, nullptr, T_SEQ, 2, 1.f);

        // x = x + y @ proj_w^T  (2-term)
        gemm_f16<2><<<dim3(T_SEQ / BMT, N_EMBD / BNT, 1), 256, SMEM2>>>(
            y, N_EMBD, 0, pw, N_EMBD, 0, 1,
            x, N_EMBD, 0, x, N_EMBD, 0, 1.f);

        rmsnorm_kernel<<<T_SEQ, 256>>>(x, norm2_w + l * N_EMBD, n);

        // MLP up projections (2-term)
        gemm_f16<2><<<dim3(T_SEQ / BMT, INTER / BNT, 1), 256, SMEM2>>>(
            n, N_EMBD, 0, w1l, N_EMBD, 0, 1,
            h1, INTER, 0, nullptr, N_EMBD, 0, 1.f);
        gemm_f16<2><<<dim3(T_SEQ / BMT, INTER / BNT, 1), 256, SMEM2>>>(
            n, N_EMBD, 0, w2l, N_EMBD, 0, 1,
            h2, INTER, 0, nullptr, N_EMBD, 0, 1.f);

        // h1 = silu(h1) * h2  (single pass, no recompute)
        swiglu_kernel<<<(T_SEQ * INTER) / 256, 256>>>(h1, h2);

        // x = x + h1 @ w3^T  (2-term)
        gemm_f16<2><<<dim3(T_SEQ / BMT, N_EMBD / BNT, 1), 256, SMEM2>>>(
            h1, INTER, 0, w3l, INTER, 0, 1,
            x, N_EMBD, 0, x, INTER, 0, 1.f);
    }

    rmsnorm_kernel<<<T_SEQ, 256>>>(x, ln_f_w, n);
    // lm_head: 1-term fp16
    gemm_f16<1><<<dim3(T_SEQ / BMT, VOCAB / BNT, 1), 256, SMEM1>>>(
        n, N_EMBD, 0, lm_head_w, N_EMBD, 0, 1,
        out, VOCAB, 0, nullptr, N_EMBD, 0, 1.f);
}

// round 11
// speedup vs baseline: 1.1432x; 1.0279x over previous
#include <cuda_runtime.h>
#include <cuda_fp16.h>
#include <math.h>
#include <stdint.h>

#define T_SEQ 2048
#define N_EMBD 2048
#define N_HEADS 16
#define N_GROUPS 4
#define HEAD_SIZE 128
#define INTER 5632
#define VOCAB 32000
#define QKV_DIM 3072
#define NTILES 16              // T_SEQ / 128

// ---------------- scratch ---------------------------------------------------
__device__ float g_x  [T_SEQ * N_EMBD];
__device__ float g_n  [T_SEQ * N_EMBD];
__device__ float g_qkv[T_SEQ * QKV_DIM];
__device__ float g_q  [N_HEADS  * T_SEQ * HEAD_SIZE];
__device__ float g_k  [N_GROUPS * T_SEQ * HEAD_SIZE];
__device__ float g_vT [N_GROUPS * HEAD_SIZE * T_SEQ];
__device__ float g_S  [N_HEADS * T_SEQ * T_SEQ];
__device__ float g_y  [2 * T_SEQ * N_EMBD];          // y1 | y2 (PV split-K halves)
__device__ float g_h1 [T_SEQ * INTER];
__device__ float g_rs [N_HEADS * T_SEQ * NTILES];    // per-tile S row sums

// ---------------- helpers ---------------------------------------------------
__device__ __forceinline__ uint32_t cvta_smem(const void* p) {
    uint32_t a;
    asm("{.reg .u64 t; cvta.to.shared.u64 t, %1; cvt.u32.u64 %0, t;}" : "=r"(a) : "l"(p));
    return a;
}

__device__ __forceinline__ void mma16(float* d, const uint32_t* a, const uint32_t* b) {
    asm volatile(
        "mma.sync.aligned.m16n8k16.row.col.f32.f16.f16.f32 "
        "{%0,%1,%2,%3}, {%4,%5,%6,%7}, {%8,%9}, {%0,%1,%2,%3};"
        : "+f"(d[0]), "+f"(d[1]), "+f"(d[2]), "+f"(d[3])
        : "r"(a[0]), "r"(a[1]), "r"(a[2]), "r"(a[3]), "r"(b[0]), "r"(b[1]));
}

__device__ __forceinline__ void ldsm4(uint32_t* r, uint32_t addr) {
    asm volatile("ldmatrix.sync.aligned.m8n8.x4.shared.b16 {%0,%1,%2,%3}, [%4];"
        : "=r"(r[0]), "=r"(r[1]), "=r"(r[2]), "=r"(r[3]) : "r"(addr));
}

__device__ __forceinline__ void split4(float4 v, uint2& hi, uint2& lo) {
    __half2 h01 = __floats2half2_rn(v.x, v.y);
    __half2 h23 = __floats2half2_rn(v.z, v.w);
    float2 f01 = __half22float2(h01);
    float2 f23 = __half22float2(h23);
    __half2 l01 = __floats2half2_rn(v.x - f01.x, v.y - f01.y);
    __half2 l23 = __floats2half2_rn(v.z - f23.x, v.w - f23.y);
    hi.x = *(uint32_t*)&h01; hi.y = *(uint32_t*)&h23;
    lo.x = *(uint32_t*)&l01; lo.y = *(uint32_t*)&l23;
}
__device__ __forceinline__ void trunc4(float4 v, uint2& hi) {
    __half2 h01 = __floats2half2_rn(v.x, v.y);
    __half2 h23 = __floats2half2_rn(v.z, v.w);
    hi.x = *(uint32_t*)&h01; hi.y = *(uint32_t*)&h23;
}

// ---------------- fp16 split NT GEMM (mma.sync m16n8k16 + ldmatrix) ---------
// C = A@B^T (+addC). TERMS=2: AhBh+AlBh (A split, B truncated); TERMS=1: AhBh.
// A2   != null: A := A + A2 elementwise (PV split-K recombine for proj)
// gluG != null: epilogue v := silu(gluG[off]) * v (once per element)
// rsum != null & mode 1: epilogue writes per-tile masked row sums
// mode: 0 plain
//       1 causal S: skip tiles above diagonal, epilogue scale+mask+rowsum
//       2 causal PV split-K: m reversed (big first), blockIdx.y = K-half,
//         A rows scaled by 1/(rowsum+1e-8) read from rsum partials
#define BMT 128
#define BNT 128
#define KB  32
#define ROWW 20
#define SUBW (128 * ROWW)

template<int TERMS>
__global__ void __launch_bounds__(256)
gemm_f16(const float* __restrict__ A, const float* __restrict__ A2, int lda, long long sA,
         const float* __restrict__ B, int ldb, long long sB, int bdiv,
         float* C, int ldc, long long sC, long long sSplit,
         const float* __restrict__ addC, const float* __restrict__ gluG,
         float* __restrict__ rsum,
         int K, int mode, float scaleC)
{
    constexpr int NA   = (TERMS >= 2) ? 2 : 1;
    constexpr int NSUB = NA + 1;
    constexpr int STGW = NSUB * SUBW;
    extern __shared__ __align__(16) uint32_t smw[];

    int m0, n0, split = 0, kbase = 0, KT, mt = 0;
    if (mode == 2) {
        m0 = (gridDim.x - 1 - blockIdx.x) * BMT;    // biggest K first
        n0 = 0;
        split = blockIdx.y;
        mt = m0 >> 7;
        int ktt = (mt + 1) * (128 / KB);            // total K-tiles (causal clamp)
        int half = ktt >> 1;
        kbase = split ? half : 0;
        KT    = split ? (ktt - half) : half;
    } else {
        m0 = blockIdx.x * BMT;
        n0 = blockIdx.y * BNT;
        if (mode == 1 && n0 > m0 + BMT - 1) return;
        KT = K / KB;
    }
    const int z = blockIdx.z;
    A += (long long)z * sA;
    if (A2) A2 += (long long)z * sA;
    B += (long long)(z / bdiv) * sB;
    const long long coff = (long long)z * sC + (long long)split * sSplit;

    const int tid  = threadIdx.x;
    const int lane = tid & 31;
    const int wid  = tid >> 5;
    const int wm   = (wid & 1) * 64;
    const int wn   = (wid >> 1) * 32;
    const uint32_t sbase = cvta_smem(smw);

    const int aRow  = wm + (lane & 15);
    const int aCol4 = (lane & 16) ? 4 : 0;
    const int bRow  = wn + (lane & 7) + ((lane & 16) ? 8 : 0);
    const int bCol4 = (lane & 8) ? 4 : 0;

    float4 rA[4], rB[4];
    const int lr = tid >> 3;
    const int lc = tid & 7;

    // ---- mode 2: row scales from precomputed per-tile S row sums ----
    float ascale[4] = {1.f, 1.f, 1.f, 1.f};
    if (mode == 2) {
        #pragma unroll
        for (int it = 0; it < 4; it++) {
            int r = m0 + it * 32 + lr;
            const float* rp = rsum + ((long long)z * T_SEQ + r) * NTILES;
            float s = 0.f;
            for (int j = 0; j <= mt; j++) s += rp[j];
            ascale[it] = 1.f / (s + 1e-8f);
        }
    }

    auto ldg_tile = [&](int kt) {
        const int kof = (kbase + kt) * KB;
        #pragma unroll
        for (int it = 0; it < 4; it++) {
            int r = it * 32 + lr;
            float4 a = *(const float4*)(A + (long long)(m0 + r) * lda + kof + lc * 4);
            if (A2) {
                float4 a2 = *(const float4*)(A2 + (long long)(m0 + r) * lda + kof + lc * 4);
                a.x += a2.x; a.y += a2.y; a.z += a2.z; a.w += a2.w;
            }
            rA[it] = a;
            rB[it] = *(const float4*)(B + (long long)(n0 + r) * ldb + kof + lc * 4);
        }
    };
    auto sts_tile = [&](int s) {
        uint32_t* st = smw + s * STGW;
        #pragma unroll
        for (int it = 0; it < 4; it++) {
            int r = it * 32 + lr;
            int w = r * ROWW + lc * 2;
            float4 av = rA[it];
            if (mode == 2) { av.x *= ascale[it]; av.y *= ascale[it]; av.z *= ascale[it]; av.w *= ascale[it]; }
            uint2 hi, lo;
            if (TERMS >= 2) {
                split4(av, hi, lo);
                *(uint2*)(st + w) = hi;
                *(uint2*)(st + SUBW + w) = lo;
            } else {
                trunc4(av, hi);
                *(uint2*)(st + w) = hi;
            }
            trunc4(rB[it], hi);
            *(uint2*)(st + NA * SUBW + w) = hi;
        }
    };

    float acc[4][4][4];
    #pragma unroll
    for (int a = 0; a < 4; a++)
        #pragma unroll
        for (int b = 0; b < 4; b++)
            #pragma unroll
            for (int c = 0; c < 4; c++) acc[a][b][c] = 0.f;

    ldg_tile(0);
    sts_tile(0);
    if (KT > 1) ldg_tile(1);
    __syncthreads();

    for (int kt = 0; kt < KT; kt++) {
        if (kt + 1 < KT) sts_tile((kt + 1) & 1);
        if (kt + 2 < KT) ldg_tile(kt + 2);

        const uint32_t stAddr = sbase + (uint32_t)((kt & 1) * STGW) * 4u;

        #pragma unroll
        for (int ks = 0; ks < 2; ks++) {
            uint32_t Ah[4][4], Al[4][4], Bh[4][2];
            #pragma unroll
            for (int mc = 0; mc < 4; mc++) {
                uint32_t off = stAddr + (uint32_t)(((aRow + mc * 16) * ROWW + aCol4 + ks * 8)) * 4u;
                ldsm4(Ah[mc], off);
                if (TERMS >= 2) ldsm4(Al[mc], off + SUBW * 4u);
            }
            #pragma unroll
            for (int ncp = 0; ncp < 2; ncp++) {
                uint32_t off = stAddr + (uint32_t)((NA * SUBW + (bRow + ncp * 16) * ROWW + bCol4 + ks * 8)) * 4u;
                uint32_t t[4];
                ldsm4(t, off);
                Bh[ncp * 2][0] = t[0]; Bh[ncp * 2][1] = t[1];
                Bh[ncp * 2 + 1][0] = t[2]; Bh[ncp * 2 + 1][1] = t[3];
            }
            #pragma unroll
            for (int mc = 0; mc < 4; mc++)
                #pragma unroll
                for (int nc = 0; nc < 4; nc++) {
                    mma16(acc[mc][nc], Ah[mc], Bh[nc]);
                    if (TERMS >= 2) mma16(acc[mc][nc], Al[mc], Bh[nc]);
                }
        }
        __syncthreads();
    }

    // ---- epilogue ----
    float rs[4][2];
    #pragma unroll
    for (int a = 0; a < 4; a++) { rs[a][0] = 0.f; rs[a][1] = 0.f; }

    #pragma unroll
    for (int mc = 0; mc < 4; mc++)
        #pragma unroll
        for (int nc = 0; nc < 4; nc++) {
            int c0 = n0 + wn + nc * 8 + (lane & 3) * 2;
            #pragma unroll
            for (int rr = 0; rr < 2; rr++) {
                int row = m0 + wm + mc * 16 + (lane >> 2) + rr * 8;
                float v0 = acc[mc][nc][rr * 2] * scaleC;
                float v1 = acc[mc][nc][rr * 2 + 1] * scaleC;
                if (mode == 1) {
                    if (c0 > row)     v0 = 0.f;
                    if (c0 + 1 > row) v1 = 0.f;
                    rs[mc][rr] += v0 + v1;
                }
                long long off = coff + (long long)row * ldc + c0;
                if (gluG) {
                    float g0 = gluG[off], g1 = gluG[off + 1];
                    v0 *= g0 / (1.f + expf(-g0));
                    v1 *= g1 / (1.f + expf(-g1));
                }
                if (addC) { v0 += addC[off]; v1 += addC[off + 1]; }
                C[off] = v0;
                C[off + 1] = v1;
            }
        }

    // ---- mode 1: per-tile row sums -> rsum[z][row][n0/128] ----
    if (mode == 1 && rsum) {
        float* red = (float*)smw;                 // 4 n-groups x 128 rows
        #pragma unroll
        for (int mc = 0; mc < 4; mc++)
            #pragma unroll
            for (int rr = 0; rr < 2; rr++) {
                float v = rs[mc][rr];
                v += __shfl_xor_sync(0xffffffffu, v, 1);
                v += __shfl_xor_sync(0xffffffffu, v, 2);
                int rtile = wm + mc * 16 + (lane >> 2) + rr * 8;
                if ((lane & 3) == 0) red[(wid >> 1) * 128 + rtile] = v;
            }
        __syncthreads();
        if (tid < 128) {
            float s = red[tid] + red[128 + tid] + red[256 + tid] + red[384 + tid];
            rsum[((long long)z * T_SEQ + (m0 + tid)) * NTILES + (n0 >> 7)] = s;
        }
    }
}

// ---------------- elementwise kernels ---------------------------------------
__global__ void embed_kernel(const int* __restrict__ idx,
                             const float* __restrict__ wte, float* __restrict__ x)
{
    int t = blockIdx.x;
    const float* src = wte + (long long)idx[t] * N_EMBD;
    float* dst = x + (long long)t * N_EMBD;
    for (int e = threadIdx.x; e < N_EMBD; e += blockDim.x) dst[e] = src[e];
}

__global__ void rmsnorm_kernel(const float* __restrict__ x, const float* __restrict__ w,
                               float* __restrict__ out)
{
    int t = blockIdx.x;
    const float* row = x + (long long)t * N_EMBD;
    float s = 0.f;
    for (int e = threadIdx.x; e < N_EMBD; e += blockDim.x) { float v = row[e]; s += v * v; }
    __shared__ float red[32];
    #pragma unroll
    for (int o = 16; o; o >>= 1) s += __shfl_xor_sync(0xffffffffu, s, o);
    if ((threadIdx.x & 31) == 0) red[threadIdx.x >> 5] = s;
    __syncthreads();
    if (threadIdx.x < 32) {
        float v = (threadIdx.x < (blockDim.x >> 5)) ? red[threadIdx.x] : 0.f;
        #pragma unroll
        for (int o = 16; o; o >>= 1) v += __shfl_xor_sync(0xffffffffu, v, o);
        if (threadIdx.x == 0) red[0] = v;
    }
    __syncthreads();
    float r = rsqrtf(red[0] * (1.f / N_EMBD) + 1e-5f);
    float* dst = out + (long long)t * N_EMBD;
    for (int e = threadIdx.x; e < N_EMBD; e += blockDim.x)
        dst[e] = row[e] * r * w[e];
}

__global__ void qkv_post_kernel(const float* __restrict__ qkv,
                                float* __restrict__ q,
                                float* __restrict__ k,
                                float* __restrict__ vT)
{
    int t = blockIdx.x;
    const float LN_BASE = 9.210340371976184f;
    for (int i = threadIdx.x; i < N_GROUPS * 6 * 64; i += blockDim.x) {
        int j    = i & 63;
        int slot = (i >> 6) % 6;
        int g    = i / (6 * 64);
        const float* src = qkv + (long long)t * QKV_DIM + (g * 6 + slot) * HEAD_SIZE;
        float x1 = src[j];
        float x2 = src[j + 64];
        if (slot < 5) {
            float theta = expf(-(2.f * j / 128.f) * LN_BASE);
            float ang = (float)t * theta;
            float sv, cv;
            sincosf(ang, &sv, &cv);
            float o1 = x1 * cv - x2 * sv;
            float o2 = x1 * sv + x2 * cv;
            o1 = (o1 > 0.f) ? (o1 + 1.f) : expf(o1);
            o2 = (o2 > 0.f) ? (o2 + 1.f) : expf(o2);
            if (slot < 4) {
                int h = g * 4 + slot;
                float* dst = q + ((long long)h * T_SEQ + t) * HEAD_SIZE;
                dst[j] = o1; dst[j + 64] = o2;
            } else {
                float* dst = k + ((long long)g * T_SEQ + t) * HEAD_SIZE;
                dst[j] = o1; dst[j + 64] = o2;
            }
        } else {
            vT[((long long)g * HEAD_SIZE + j) * T_SEQ + t]      = x1;
            vT[((long long)g * HEAD_SIZE + j + 64) * T_SEQ + t] = x2;
        }
    }
}

// ---------------- orchestration ---------------------------------------------
extern "C" void kernel_launch(void* const* d_in, const int* in_sizes, int n_in,
                              void* d_out, int out_size)
{
    const int*   idx       = (const int*)  d_in[0];
    const float* wte       = (const float*)d_in[1];
    const float* attn_w    = (const float*)d_in[2];
    const float* proj_w    = (const float*)d_in[3];
    const float* w1        = (const float*)d_in[4];
    const float* w2        = (const float*)d_in[5];
    const float* w3        = (const float*)d_in[6];
    const float* norm1_w   = (const float*)d_in[7];
    const float* norm2_w   = (const float*)d_in[8];
    const float* ln_f_w    = (const float*)d_in[9];
    const float* lm_head_w = (const float*)d_in[10];
    float* out = (float*)d_out;

    float *x, *n, *qkv, *q, *k, *vT, *S, *y, *h1, *rsum;
    cudaGetSymbolAddress((void**)&x,    g_x);
    cudaGetSymbolAddress((void**)&n,    g_n);
    cudaGetSymbolAddress((void**)&qkv,  g_qkv);
    cudaGetSymbolAddress((void**)&q,    g_q);
    cudaGetSymbolAddress((void**)&k,    g_k);
    cudaGetSymbolAddress((void**)&vT,   g_vT);
    cudaGetSymbolAddress((void**)&S,    g_S);
    cudaGetSymbolAddress((void**)&y,    g_y);
    cudaGetSymbolAddress((void**)&h1,   g_h1);
    cudaGetSymbolAddress((void**)&rsum, g_rs);

    const int SMEM2 = 2 * 3 * SUBW * 4;   // 61440 B
    const int SMEM1 = 2 * 2 * SUBW * 4;   // 40960 B
    cudaFuncSetAttribute(gemm_f16<2>, cudaFuncAttributeMaxDynamicSharedMemorySize, SMEM2);
    cudaFuncSetAttribute(gemm_f16<1>, cudaFuncAttributeMaxDynamicSharedMemorySize, SMEM1);

    const long long TT = (long long)T_SEQ * T_SEQ;
    const long long TH = (long long)T_SEQ * HEAD_SIZE;
    const long long YSPLIT = (long long)T_SEQ * N_EMBD;
    const float SSCALE = 0.08838834764831845f;   // 1/sqrt(128)

    embed_kernel<<<T_SEQ, 256>>>(idx, wte, x);

    for (int l = 0; l < 2; l++) {
        const float* aw  = attn_w + (long long)l * QKV_DIM * N_EMBD;
        const float* pw  = proj_w + (long long)l * N_EMBD * N_EMBD;
        const float* w1l = w1 + (long long)l * INTER * N_EMBD;
        const float* w2l = w2 + (long long)l * INTER * N_EMBD;
        const float* w3l = w3 + (long long)l * N_EMBD * INTER;

        rmsnorm_kernel<<<T_SEQ, 256>>>(x, norm1_w + l * N_EMBD, n);

        // qkv = n1 @ attn_w^T
        gemm_f16<2><<<dim3(T_SEQ / BMT, QKV_DIM / BNT, 1), 256, SMEM2>>>(
            n, nullptr, N_EMBD, 0, aw, N_EMBD, 0, 1,
            qkv, QKV_DIM, 0, 0, nullptr, nullptr, nullptr, N_EMBD, 0, 1.f);

        qkv_post_kernel<<<T_SEQ, 512>>>(qkv, q, k, vT);

        // S[h] = mask(q[h] @ k[g]^T * scale), epilogue emits per-tile row sums
        gemm_f16<2><<<dim3(T_SEQ / BMT, T_SEQ / BNT, N_HEADS), 256, SMEM2>>>(
            q, nullptr, HEAD_SIZE, TH, k, HEAD_SIZE, TH, 4,
            S, T_SEQ, TT, 0, nullptr, nullptr, rsum, HEAD_SIZE, 1, SSCALE);

        // y1|y2 halves: (S/rowsum)[h] @ vT[g]^T, split-K over the causal range
        gemm_f16<2><<<dim3(T_SEQ / BMT, 2, N_HEADS), 256, SMEM2>>>(
            S, nullptr, T_SEQ, TT, vT, T_SEQ, (long long)HEAD_SIZE * T_SEQ, 4,
            y, N_EMBD, HEAD_SIZE, YSPLIT, nullptr, nullptr, rsum, T_SEQ, 2, 1.f);

        // x = x + (y1+y2) @ proj_w^T
        gemm_f16<2><<<dim3(T_SEQ / BMT, N_EMBD / BNT, 1), 256, SMEM2>>>(
            y, y + YSPLIT, N_EMBD, 0, pw, N_EMBD, 0, 1,
            x, N_EMBD, 0, 0, x, nullptr, nullptr, N_EMBD, 0, 1.f);

        rmsnorm_kernel<<<T_SEQ, 256>>>(x, norm2_w + l * N_EMBD, n);

        // h1 = n2 @ w1^T
        gemm_f16<2><<<dim3(T_SEQ / BMT, INTER / BNT, 1), 256, SMEM2>>>(
            n, nullptr, N_EMBD, 0, w1l, N_EMBD, 0, 1,
            h1, INTER, 0, 0, nullptr, nullptr, nullptr, N_EMBD, 0, 1.f);
        // h1 = silu(h1) * (n2 @ w2^T)   (GLU fused in epilogue, once/element)
        gemm_f16<2><<<dim3(T_SEQ / BMT, INTER / BNT, 1), 256, SMEM2>>>(
            n, nullptr, N_EMBD, 0, w2l, N_EMBD, 0, 1,
            h1, INTER, 0, 0, nullptr, h1, nullptr, N_EMBD, 0, 1.f);

        // x = x + h1 @ w3^T
        gemm_f16<2><<<dim3(T_SEQ / BMT, N_EMBD / BNT, 1), 256, SMEM2>>>(
            h1, nullptr, INTER, 0, w3l, INTER, 0, 1,
            x, N_EMBD, 0, 0, x, nullptr, nullptr, INTER, 0, 1.f);
    }

    rmsnorm_kernel<<<T_SEQ, 256>>>(x, ln_f_w, n);
    // lm_head: 1-term fp16
    gemm_f16<1><<<dim3(T_SEQ / BMT, VOCAB / BNT, 1), 256, SMEM1>>>(
        n, nullptr, N_EMBD, 0, lm_head_w, N_EMBD, 0, 1,
        out, VOCAB, 0, 0, nullptr, nullptr, nullptr, N_EMBD, 0, 1.f);
}

// round 12
// speedup vs baseline: 1.3307x; 1.1640x over previous
#include <cuda_runtime.h>
#include <cuda_fp16.h>
#include <math.h>
#include <stdint.h>

#define T_SEQ 2048
#define N_EMBD 2048
#define N_HEADS 16
#define N_GROUPS 4
#define HEAD_SIZE 128
#define INTER 5632
#define VOCAB 32000
#define QKV_DIM 3072
#define NTILES 16              // T_SEQ / 128

// ---------------- scratch ---------------------------------------------------
__device__ float  g_x  [T_SEQ * N_EMBD];
__device__ float  g_qkv[T_SEQ * QKV_DIM];
__device__ float  g_S  [N_HEADS * T_SEQ * T_SEQ];
__device__ float  g_y  [2 * T_SEQ * N_EMBD];          // y1 | y2 (PV split-K)
__device__ float  g_rs [N_HEADS * T_SEQ * NTILES];    // per-tile S row sums
// fp16 activations (hi/lo pairs where GEMM A operand, hi-only where B)
__device__ __half g_nh [T_SEQ * N_EMBD];
__device__ __half g_nl [T_SEQ * N_EMBD];
__device__ __half g_qh [N_HEADS  * T_SEQ * HEAD_SIZE];
__device__ __half g_ql [N_HEADS  * T_SEQ * HEAD_SIZE];
__device__ __half g_k16[N_GROUPS * T_SEQ * HEAD_SIZE];
__device__ __half g_v16[N_GROUPS * HEAD_SIZE * T_SEQ];
__device__ __half g_h1h[T_SEQ * INTER];
__device__ __half g_h1l[T_SEQ * INTER];
// fp16 weights (truncated per replay)
__device__ __half g_aw16[2 * QKV_DIM * N_EMBD];
__device__ __half g_pw16[2 * N_EMBD * N_EMBD];
__device__ __half g_w116[2 * INTER * N_EMBD];
__device__ __half g_w216[2 * INTER * N_EMBD];
__device__ __half g_w316[2 * N_EMBD * INTER];
__device__ __half g_lm16[VOCAB * N_EMBD];

// ---------------- helpers ---------------------------------------------------
__device__ __forceinline__ uint32_t cvta_smem(const void* p) {
    uint32_t a;
    asm("{.reg .u64 t; cvta.to.shared.u64 t, %1; cvt.u32.u64 %0, t;}" : "=r"(a) : "l"(p));
    return a;
}

__device__ __forceinline__ void mma16(float* d, const uint32_t* a, const uint32_t* b) {
    asm volatile(
        "mma.sync.aligned.m16n8k16.row.col.f32.f16.f16.f32 "
        "{%0,%1,%2,%3}, {%4,%5,%6,%7}, {%8,%9}, {%0,%1,%2,%3};"
        : "+f"(d[0]), "+f"(d[1]), "+f"(d[2]), "+f"(d[3])
        : "r"(a[0]), "r"(a[1]), "r"(a[2]), "r"(a[3]), "r"(b[0]), "r"(b[1]));
}

__device__ __forceinline__ void ldsm4(uint32_t* r, uint32_t addr) {
    asm volatile("ldmatrix.sync.aligned.m8n8.x4.shared.b16 {%0,%1,%2,%3}, [%4];"
        : "=r"(r[0]), "=r"(r[1]), "=r"(r[2]), "=r"(r[3]) : "r"(addr));
}

#define CP16(dst, src) asm volatile("cp.async.cg.shared.global [%0], [%1], 16;" :: "r"(dst), "l"(src))
#define CP_COMMIT() asm volatile("cp.async.commit_group;" ::: "memory")

__device__ __forceinline__ void split4(float4 v, uint2& hi, uint2& lo) {
    __half2 h01 = __floats2half2_rn(v.x, v.y);
    __half2 h23 = __floats2half2_rn(v.z, v.w);
    float2 f01 = __half22float2(h01);
    float2 f23 = __half22float2(h23);
    __half2 l01 = __floats2half2_rn(v.x - f01.x, v.y - f01.y);
    __half2 l23 = __floats2half2_rn(v.z - f23.x, v.w - f23.y);
    hi.x = *(uint32_t*)&h01; hi.y = *(uint32_t*)&h23;
    lo.x = *(uint32_t*)&l01; lo.y = *(uint32_t*)&l23;
}

// ---------------- fp16 NT GEMM (mma.sync m16n8k16 + ldmatrix) ---------------
// C = A@B^T (+addC). TERMS=2: AhBh+AlBh; TERMS=1: AhBh.
// AF=0: A is fp16 hi/lo pair in gmem, loaded via cp.async (3-stage ring)
// AF=1: A is fp32 (+optional A2 add, +mode-2 row scaling), register split
// B is always fp16 in gmem.
// mode: 0 plain; 1 causal S (tile skip, scale+mask+rowsum epilogue);
//       2 causal PV split-K (AF=1): m reversed, blockIdx.y = K-half,
//       A rows scaled by 1/(rowsum+1e-8)
#define BMT 128
#define BNT 128
#define KB  32
#define ROWW 20
#define SUBW (128 * ROWW)

template<int TERMS, int AF>
__global__ void __launch_bounds__(256, AF == 0 ? 2 : 1)
gemm_f16(const __half* __restrict__ Ah16, const __half* __restrict__ Al16,
         const float* __restrict__ Af, const float* __restrict__ A2f,
         int lda, long long sA,
         const __half* __restrict__ B16, int ldb, long long sB, int bdiv,
         float* C, __half* Ch, __half* Cl, int ldc, long long sC, long long sSplit,
         const float* __restrict__ addC,
         const __half* __restrict__ gGh, const __half* __restrict__ gGl,
         float* __restrict__ rsum,
         int K, int mode, float scaleC)
{
    constexpr int NA     = (TERMS >= 2) ? 2 : 1;
    constexpr int NSUB   = NA + 1;
    constexpr int STGW   = NSUB * SUBW;
    constexpr int STAGES = (AF == 0) ? 3 : 2;
    extern __shared__ __align__(16) uint32_t smw[];

    int m0, n0, split = 0, kbase = 0, KT, mt = 0;
    if (mode == 2) {
        m0 = (gridDim.x - 1 - blockIdx.x) * BMT;    // biggest K first
        n0 = 0;
        split = blockIdx.y;
        mt = m0 >> 7;
        int ktt = (mt + 1) * (128 / KB);
        int half = ktt >> 1;
        kbase = split ? half : 0;
        KT    = split ? (ktt - half) : half;
    } else {
        m0 = blockIdx.x * BMT;
        n0 = blockIdx.y * BNT;
        if (mode == 1 && n0 > m0 + BMT - 1) return;
        KT = K / KB;
    }
    const int z = blockIdx.z;
    if (AF == 0) {
        Ah16 += (long long)z * sA;
        if (TERMS >= 2) Al16 += (long long)z * sA;
    } else {
        Af += (long long)z * sA;
        if (A2f) A2f += (long long)z * sA;
    }
    B16 += (long long)(z / bdiv) * sB;
    const long long coff = (long long)z * sC + (long long)split * sSplit;

    const int tid  = threadIdx.x;
    const int lane = tid & 31;
    const int wid  = tid >> 5;
    const int wm   = (wid & 1) * 64;
    const int wn   = (wid >> 1) * 32;
    const uint32_t sbase = cvta_smem(smw);

    const int aRow  = wm + (lane & 15);
    const int aCol4 = (lane & 16) ? 4 : 0;
    const int bRow  = wn + (lane & 7) + ((lane & 16) ? 8 : 0);
    const int bCol4 = (lane & 8) ? 4 : 0;

    // ---- mode 2 (AF=1): row scales from per-tile S row sums ----
    float ascale[4] = {1.f, 1.f, 1.f, 1.f};
    const int lr = tid >> 3;
    const int lc = tid & 7;
    if (AF == 1 && mode == 2) {
        #pragma unroll
        for (int it = 0; it < 4; it++) {
            int r = m0 + it * 32 + lr;
            const float* rp = rsum + ((long long)z * T_SEQ + r) * NTILES;
            float s = 0.f;
            for (int j = 0; j <= mt; j++) s += rp[j];
            ascale[it] = 1.f / (s + 1e-8f);
        }
    }

    // ---- AF=0 loader: cp.async fp16 direct ----
    auto cp_tile = [&](int kt) {
        const int kof = (kbase + kt) * KB;
        const uint32_t st = sbase + (uint32_t)((kt % STAGES) * STGW) * 4u;
        #pragma unroll
        for (int it = 0; it < 2; it++) {
            int id = it * 256 + tid;
            int r = id >> 2, c = id & 3;
            uint32_t w4 = (uint32_t)(r * ROWW + c * 4) * 4u;
            CP16(st + w4, (const char*)(Ah16 + (long long)(m0 + r) * lda + kof) + c * 16);
            if (TERMS >= 2)
                CP16(st + SUBW * 4u + w4,
                     (const char*)(Al16 + (long long)(m0 + r) * lda + kof) + c * 16);
            CP16(st + NA * SUBW * 4u + w4,
                 (const char*)(B16 + (long long)(n0 + r) * ldb + kof) + c * 16);
        }
        CP_COMMIT();
    };

    // ---- AF=1 loader: fp32 A (ldg+split) + fp16 B (ldg) ----
    float4 rA[4];
    uint4  rBu[2];
    auto ldg_tile = [&](int kt) {
        const int kof = (kbase + kt) * KB;
        #pragma unroll
        for (int it = 0; it < 4; it++) {
            int r = it * 32 + lr;
            float4 a = *(const float4*)(Af + (long long)(m0 + r) * lda + kof + lc * 4);
            if (A2f) {
                float4 a2 = *(const float4*)(A2f + (long long)(m0 + r) * lda + kof + lc * 4);
                a.x += a2.x; a.y += a2.y; a.z += a2.z; a.w += a2.w;
            }
            rA[it] = a;
        }
        #pragma unroll
        for (int it = 0; it < 2; it++) {
            int id = it * 256 + tid;
            int r = id >> 2, c = id & 3;
            rBu[it] = *(const uint4*)((const char*)(B16 + (long long)(n0 + r) * ldb + kof) + c * 16);
        }
    };
    auto sts_tile = [&](int s) {
        uint32_t* st = smw + s * STGW;
        #pragma unroll
        for (int it = 0; it < 4; it++) {
            int r = it * 32 + lr;
            int w = r * ROWW + lc * 2;
            float4 av = rA[it];
            if (mode == 2) { av.x *= ascale[it]; av.y *= ascale[it]; av.z *= ascale[it]; av.w *= ascale[it]; }
            uint2 hi, lo;
            split4(av, hi, lo);
            *(uint2*)(st + w) = hi;
            *(uint2*)(st + SUBW + w) = lo;
        }
        #pragma unroll
        for (int it = 0; it < 2; it++) {
            int id = it * 256 + tid;
            int r = id >> 2, c = id & 3;
            *(uint4*)(st + NA * SUBW + r * ROWW + c * 4) = rBu[it];
        }
    };

    float acc[4][4][4];
    #pragma unroll
    for (int a = 0; a < 4; a++)
        #pragma unroll
        for (int b = 0; b < 4; b++)
            #pragma unroll
            for (int c = 0; c < 4; c++) acc[a][b][c] = 0.f;

    // ---- pipeline ----
    if (AF == 0) {
        cp_tile(0);
        if (KT > 1) cp_tile(1);
    } else {
        ldg_tile(0);
        sts_tile(0);
        if (KT > 1) ldg_tile(1);
        __syncthreads();
    }

    for (int kt = 0; kt < KT; kt++) {
        if (AF == 0) {
            if (kt + 1 < KT) asm volatile("cp.async.wait_group 1;" ::: "memory");
            else             asm volatile("cp.async.wait_group 0;" ::: "memory");
            __syncthreads();
            if (kt + 2 < KT) cp_tile(kt + 2);
        } else {
            if (kt + 1 < KT) sts_tile((kt + 1) & 1);
            if (kt + 2 < KT) ldg_tile(kt + 2);
        }

        const uint32_t stAddr = sbase + (uint32_t)((kt % STAGES) * STGW) * 4u;

        #pragma unroll
        for (int ks = 0; ks < 2; ks++) {
            uint32_t Ah[4][4], Al[4][4], Bh[4][2];
            #pragma unroll
            for (int mc = 0; mc < 4; mc++) {
                uint32_t off = stAddr + (uint32_t)(((aRow + mc * 16) * ROWW + aCol4 + ks * 8)) * 4u;
                ldsm4(Ah[mc], off);
                if (TERMS >= 2) ldsm4(Al[mc], off + SUBW * 4u);
            }
            #pragma unroll
            for (int ncp = 0; ncp < 2; ncp++) {
                uint32_t off = stAddr + (uint32_t)((NA * SUBW + (bRow + ncp * 16) * ROWW + bCol4 + ks * 8)) * 4u;
                uint32_t t[4];
                ldsm4(t, off);
                Bh[ncp * 2][0] = t[0]; Bh[ncp * 2][1] = t[1];
                Bh[ncp * 2 + 1][0] = t[2]; Bh[ncp * 2 + 1][1] = t[3];
            }
            #pragma unroll
            for (int mc = 0; mc < 4; mc++)
                #pragma unroll
                for (int nc = 0; nc < 4; nc++) {
                    mma16(acc[mc][nc], Ah[mc], Bh[nc]);
                    if (TERMS >= 2) mma16(acc[mc][nc], Al[mc], Bh[nc]);
                }
        }
        if (AF == 1) __syncthreads();
    }

    // ---- epilogue ----
    float rs[4][2];
    #pragma unroll
    for (int a = 0; a < 4; a++) { rs[a][0] = 0.f; rs[a][1] = 0.f; }

    #pragma unroll
    for (int mc = 0; mc < 4; mc++)
        #pragma unroll
        for (int nc = 0; nc < 4; nc++) {
            int c0 = n0 + wn + nc * 8 + (lane & 3) * 2;
            #pragma unroll
            for (int rr = 0; rr < 2; rr++) {
                int row = m0 + wm + mc * 16 + (lane >> 2) + rr * 8;
                float v0 = acc[mc][nc][rr * 2] * scaleC;
                float v1 = acc[mc][nc][rr * 2 + 1] * scaleC;
                if (mode == 1) {
                    if (c0 > row)     v0 = 0.f;
                    if (c0 + 1 > row) v1 = 0.f;
                    rs[mc][rr] += v0 + v1;
                }
                long long off = coff + (long long)row * ldc + c0;
                if (gGh) {
                    float g0 = __half2float(gGh[off]) + __half2float(gGl[off]);
                    float g1 = __half2float(gGh[off + 1]) + __half2float(gGl[off + 1]);
                    v0 *= g0 / (1.f + expf(-g0));
                    v1 *= g1 / (1.f + expf(-g1));
                }
                if (addC) { v0 += addC[off]; v1 += addC[off + 1]; }
                if (C) { C[off] = v0; C[off + 1] = v1; }
                if (Ch) {
                    __half2 h2 = __floats2half2_rn(v0, v1);
                    float2 hf = __half22float2(h2);
                    __half2 l2 = __floats2half2_rn(v0 - hf.x, v1 - hf.y);
                    *(__half2*)(Ch + off) = h2;
                    *(__half2*)(Cl + off) = l2;
                }
            }
        }

    // ---- mode 1: per-tile row sums -> rsum[z][row][n0/128] ----
    if (mode == 1 && rsum) {
        __syncthreads();                           // smw may still be read by laggards
        float* red = (float*)smw;
        #pragma unroll
        for (int mc = 0; mc < 4; mc++)
            #pragma unroll
            for (int rr = 0; rr < 2; rr++) {
                float v = rs[mc][rr];
                v += __shfl_xor_sync(0xffffffffu, v, 1);
                v += __shfl_xor_sync(0xffffffffu, v, 2);
                int rtile = wm + mc * 16 + (lane >> 2) + rr * 8;
                if ((lane & 3) == 0) red[(wid >> 1) * 128 + rtile] = v;
            }
        __syncthreads();
        if (tid < 128) {
            float s = red[tid] + red[128 + tid] + red[256 + tid] + red[384 + tid];
            rsum[((long long)z * T_SEQ + (m0 + tid)) * NTILES + (n0 >> 7)] = s;
        }
    }
}

// ---------------- elementwise kernels ---------------------------------------
__global__ void trunc_kernel(const float4* __restrict__ src, uint2* __restrict__ dst, int n4)
{
    int i = blockIdx.x * blockDim.x + threadIdx.x;
    if (i < n4) {
        float4 v = src[i];
        __half2 a = __floats2half2_rn(v.x, v.y);
        __half2 b = __floats2half2_rn(v.z, v.w);
        uint2 o;
        o.x = *(uint32_t*)&a; o.y = *(uint32_t*)&b;
        dst[i] = o;
    }
}

__global__ void embed_kernel(const int* __restrict__ idx,
                             const float* __restrict__ wte, float* __restrict__ x)
{
    int t = blockIdx.x;
    const float* src = wte + (long long)idx[t] * N_EMBD;
    float* dst = x + (long long)t * N_EMBD;
    for (int e = threadIdx.x; e < N_EMBD; e += blockDim.x) dst[e] = src[e];
}

__global__ void rmsnorm_kernel(const float* __restrict__ x, const float* __restrict__ w,
                               __half* __restrict__ ohi, __half* __restrict__ olo)
{
    int t = blockIdx.x;
    const float* row = x + (long long)t * N_EMBD;
    float s = 0.f;
    for (int e = threadIdx.x; e < N_EMBD; e += blockDim.x) { float v = row[e]; s += v * v; }
    __shared__ float red[32];
    #pragma unroll
    for (int o = 16; o; o >>= 1) s += __shfl_xor_sync(0xffffffffu, s, o);
    if ((threadIdx.x & 31) == 0) red[threadIdx.x >> 5] = s;
    __syncthreads();
    if (threadIdx.x < 32) {
        float v = (threadIdx.x < (blockDim.x >> 5)) ? red[threadIdx.x] : 0.f;
        #pragma unroll
        for (int o = 16; o; o >>= 1) v += __shfl_xor_sync(0xffffffffu, v, o);
        if (threadIdx.x == 0) red[0] = v;
    }
    __syncthreads();
    float r = rsqrtf(red[0] * (1.f / N_EMBD) + 1e-5f);
    for (int e = threadIdx.x; e < N_EMBD; e += blockDim.x) {
        float v = row[e] * r * w[e];
        __half h = __float2half_rn(v);
        long long i = (long long)t * N_EMBD + e;
        ohi[i] = h;
        olo[i] = __float2half_rn(v - __half2float(h));
    }
}

__global__ void qkv_post_kernel(const float* __restrict__ qkv,
                                __half* __restrict__ qh, __half* __restrict__ ql,
                                __half* __restrict__ k16, __half* __restrict__ v16)
{
    int t = blockIdx.x;
    const float LN_BASE = 9.210340371976184f;
    for (int i = threadIdx.x; i < N_GROUPS * 6 * 64; i += blockDim.x) {
        int j    = i & 63;
        int slot = (i >> 6) % 6;
        int g    = i / (6 * 64);
        const float* src = qkv + (long long)t * QKV_DIM + (g * 6 + slot) * HEAD_SIZE;
        float x1 = src[j];
        float x2 = src[j + 64];
        if (slot < 5) {
            float theta = expf(-(2.f * j / 128.f) * LN_BASE);
            float ang = (float)t * theta;
            float sv, cv;
            sincosf(ang, &sv, &cv);
            float o1 = x1 * cv - x2 * sv;
            float o2 = x1 * sv + x2 * cv;
            o1 = (o1 > 0.f) ? (o1 + 1.f) : expf(o1);
            o2 = (o2 > 0.f) ? (o2 + 1.f) : expf(o2);
            if (slot < 4) {
                int h = g * 4 + slot;
                long long b = ((long long)h * T_SEQ + t) * HEAD_SIZE;
                __half h1 = __float2half_rn(o1);
                __half h2 = __float2half_rn(o2);
                qh[b + j]      = h1;
                qh[b + j + 64] = h2;
                ql[b + j]      = __float2half_rn(o1 - __half2float(h1));
                ql[b + j + 64] = __float2half_rn(o2 - __half2float(h2));
            } else {
                long long b = ((long long)g * T_SEQ + t) * HEAD_SIZE;
                k16[b + j]      = __float2half_rn(o1);
                k16[b + j + 64] = __float2half_rn(o2);
            }
        } else {
            v16[((long long)g * HEAD_SIZE + j) * T_SEQ + t]      = __float2half_rn(x1);
            v16[((long long)g * HEAD_SIZE + j + 64) * T_SEQ + t] = __float2half_rn(x2);
        }
    }
}

// ---------------- orchestration ---------------------------------------------
extern "C" void kernel_launch(void* const* d_in, const int* in_sizes, int n_in,
                              void* d_out, int out_size)
{
    const int*   idx       = (const int*)  d_in[0];
    const float* wte       = (const float*)d_in[1];
    const float* attn_w    = (const float*)d_in[2];
    const float* proj_w    = (const float*)d_in[3];
    const float* w1        = (const float*)d_in[4];
    const float* w2        = (const float*)d_in[5];
    const float* w3        = (const float*)d_in[6];
    const float* norm1_w   = (const float*)d_in[7];
    const float* norm2_w   = (const float*)d_in[8];
    const float* ln_f_w    = (const float*)d_in[9];
    const float* lm_head_w = (const float*)d_in[10];
    float* out = (float*)d_out;

    float *x, *qkv, *S, *y, *rsum;
    __half *nh, *nl, *qh, *ql, *k16, *v16, *h1h, *h1l;
    __half *aw16, *pw16, *w116, *w216, *w316, *lm16;
    cudaGetSymbolAddress((void**)&x,    g_x);
    cudaGetSymbolAddress((void**)&qkv,  g_qkv);
    cudaGetSymbolAddress((void**)&S,    g_S);
    cudaGetSymbolAddress((void**)&y,    g_y);
    cudaGetSymbolAddress((void**)&rsum, g_rs);
    cudaGetSymbolAddress((void**)&nh,   g_nh);
    cudaGetSymbolAddress((void**)&nl,   g_nl);
    cudaGetSymbolAddress((void**)&qh,   g_qh);
    cudaGetSymbolAddress((void**)&ql,   g_ql);
    cudaGetSymbolAddress((void**)&k16,  g_k16);
    cudaGetSymbolAddress((void**)&v16,  g_v16);
    cudaGetSymbolAddress((void**)&h1h,  g_h1h);
    cudaGetSymbolAddress((void**)&h1l,  g_h1l);
    cudaGetSymbolAddress((void**)&aw16, g_aw16);
    cudaGetSymbolAddress((void**)&pw16, g_pw16);
    cudaGetSymbolAddress((void**)&w116, g_w116);
    cudaGetSymbolAddress((void**)&w216, g_w216);
    cudaGetSymbolAddress((void**)&w316, g_w316);
    cudaGetSymbolAddress((void**)&lm16, g_lm16);

    const int SM_A0T2 = 3 * 3 * SUBW * 4;   // 92160 B
    const int SM_A0T1 = 3 * 2 * SUBW * 4;   // 61440 B
    const int SM_A1T2 = 2 * 3 * SUBW * 4;   // 61440 B
    cudaFuncSetAttribute((gemm_f16<2, 0>), cudaFuncAttributeMaxDynamicSharedMemorySize, SM_A0T2);
    cudaFuncSetAttribute((gemm_f16<1, 0>), cudaFuncAttributeMaxDynamicSharedMemorySize, SM_A0T1);
    cudaFuncSetAttribute((gemm_f16<2, 1>), cudaFuncAttributeMaxDynamicSharedMemorySize, SM_A1T2);

    const long long TT = (long long)T_SEQ * T_SEQ;
    const long long TH = (long long)T_SEQ * HEAD_SIZE;
    const long long YSPLIT = (long long)T_SEQ * N_EMBD;
    const float SSCALE = 0.08838834764831845f;

    // per-replay weight truncation to fp16
    {
        int n;
        n = 2 * QKV_DIM * N_EMBD / 4; trunc_kernel<<<(n + 255) / 256, 256>>>((const float4*)attn_w, (uint2*)aw16, n);
        n = 2 * N_EMBD * N_EMBD / 4;  trunc_kernel<<<(n + 255) / 256, 256>>>((const float4*)proj_w, (uint2*)pw16, n);
        n = 2 * INTER * N_EMBD / 4;   trunc_kernel<<<(n + 255) / 256, 256>>>((const float4*)w1, (uint2*)w116, n);
        n = 2 * INTER * N_EMBD / 4;   trunc_kernel<<<(n + 255) / 256, 256>>>((const float4*)w2, (uint2*)w216, n);
        n = 2 * N_EMBD * INTER / 4;   trunc_kernel<<<(n + 255) / 256, 256>>>((const float4*)w3, (uint2*)w316, n);
        n = VOCAB * N_EMBD / 4;       trunc_kernel<<<(n + 255) / 256, 256>>>((const float4*)lm_head_w, (uint2*)lm16, n);
    }

    embed_kernel<<<T_SEQ, 256>>>(idx, wte, x);

    for (int l = 0; l < 2; l++) {
        __half* awl = aw16 + (long long)l * QKV_DIM * N_EMBD;
        __half* pwl = pw16 + (long long)l * N_EMBD * N_EMBD;
        __half* w1l = w116 + (long long)l * INTER * N_EMBD;
        __half* w2l = w216 + (long long)l * INTER * N_EMBD;
        __half* w3l = w316 + (long long)l * N_EMBD * INTER;

        rmsnorm_kernel<<<T_SEQ, 256>>>(x, norm1_w + l * N_EMBD, nh, nl);

        // qkv = n1 @ attn_w^T
        gemm_f16<2, 0><<<dim3(T_SEQ / BMT, QKV_DIM / BNT, 1), 256, SM_A0T2>>>(
            nh, nl, nullptr, nullptr, N_EMBD, 0, awl, N_EMBD, 0, 1,
            qkv, nullptr, nullptr, QKV_DIM, 0, 0,
            nullptr, nullptr, nullptr, nullptr, N_EMBD, 0, 1.f);

        qkv_post_kernel<<<T_SEQ, 512>>>(qkv, qh, ql, k16, v16);

        // S = mask(q @ k^T * scale) + per-tile row sums
        gemm_f16<2, 0><<<dim3(T_SEQ / BMT, T_SEQ / BNT, N_HEADS), 256, SM_A0T2>>>(
            qh, ql, nullptr, nullptr, HEAD_SIZE, TH, k16, HEAD_SIZE, TH, 4,
            S, nullptr, nullptr, T_SEQ, TT, 0,
            nullptr, nullptr, nullptr, rsum, HEAD_SIZE, 1, SSCALE);

        // y halves: (S/rowsum) @ vT^T, split-K over causal range
        gemm_f16<2, 1><<<dim3(T_SEQ / BMT, 2, N_HEADS), 256, SM_A1T2>>>(
            nullptr, nullptr, S, nullptr, T_SEQ, TT, v16, T_SEQ, (long long)HEAD_SIZE * T_SEQ, 4,
            y, nullptr, nullptr, N_EMBD, HEAD_SIZE, YSPLIT,
            nullptr, nullptr, nullptr, rsum, T_SEQ, 2, 1.f);

        // x = x + (y1+y2) @ proj_w^T
        gemm_f16<2, 1><<<dim3(T_SEQ / BMT, N_EMBD / BNT, 1), 256, SM_A1T2>>>(
            nullptr, nullptr, y, y + YSPLIT, N_EMBD, 0, pwl, N_EMBD, 0, 1,
            x, nullptr, nullptr, N_EMBD, 0, 0,
            x, nullptr, nullptr, nullptr, N_EMBD, 0, 1.f);

        rmsnorm_kernel<<<T_SEQ, 256>>>(x, norm2_w + l * N_EMBD, nh, nl);

        // h1 = n2 @ w1^T  (written as fp16 hi/lo pair)
        gemm_f16<2, 0><<<dim3(T_SEQ / BMT, INTER / BNT, 1), 256, SM_A0T2>>>(
            nh, nl, nullptr, nullptr, N_EMBD, 0, w1l, N_EMBD, 0, 1,
            nullptr, h1h, h1l, INTER, 0, 0,
            nullptr, nullptr, nullptr, nullptr, N_EMBD, 0, 1.f);
        // h1 = silu(h1) * (n2 @ w2^T)  (GLU fused in epilogue, once/element)
        gemm_f16<2, 0><<<dim3(T_SEQ / BMT, INTER / BNT, 1), 256, SM_A0T2>>>(
            nh, nl, nullptr, nullptr, N_EMBD, 0, w2l, N_EMBD, 0, 1,
            nullptr, h1h, h1l, INTER, 0, 0,
            nullptr, h1h, h1l, nullptr, N_EMBD, 0, 1.f);

        // x = x + h1 @ w3^T
        gemm_f16<2, 0><<<dim3(T_SEQ / BMT, N_EMBD / BNT, 1), 256, SM_A0T2>>>(
            h1h, h1l, nullptr, nullptr, INTER, 0, w3l, INTER, 0, 1,
            x, nullptr, nullptr, N_EMBD, 0, 0,
            x, nullptr, nullptr, nullptr, INTER, 0, 1.f);
    }

    rmsnorm_kernel<<<T_SEQ, 256>>>(x, ln_f_w, nh, nl);
    // lm_head: 1-term fp16
    gemm_f16<1, 0><<<dim3(T_SEQ / BMT, VOCAB / BNT, 1), 256, SM_A0T1>>>(
        nh, nullptr, nullptr, nullptr, N_EMBD, 0, lm16, N_EMBD, 0, 1,
        out, nullptr, nullptr, VOCAB, 0, 0,
        nullptr, nullptr, nullptr, nullptr, N_EMBD, 0, 1.f);
}